// round 1
// baseline (speedup 1.0000x reference)
#include <cuda_runtime.h>

#define NIMG 8
#define CDIM 512
#define HDIM 32
#define WDIM 32
#define ODIM 512
#define KW   5
#define HH   28
#define WWN  28
#define NWIN (NIMG*HH*WWN)      // 6272
#define NPIX (NIMG*HDIM*WDIM)   // 8192
#define LNEPS 1e-5f

// scratch (no allocations allowed)
__device__ float g_score[NPIX];
__device__ float g_xagg[(size_t)NWIN * CDIM];   // 12.85 MB

union f2u { float2 f; unsigned long long u; };

__device__ __forceinline__ void fma_x2(f2u& acc, const f2u& a, const f2u& b) {
    asm("fma.rn.f32x2 %0, %1, %2, %0;" : "+l"(acc.u) : "l"(a.u), "l"(b.u));
}

// ---------------------------------------------------------------------------
// K1: score[p] = dot(xr[p,:], score_w) + score_b   (one warp per pixel)
// ---------------------------------------------------------------------------
__global__ void score_kernel(const float* __restrict__ x,
                             const float* __restrict__ sw,
                             const float* __restrict__ sb) {
    int gwarp = (blockIdx.x * blockDim.x + threadIdx.x) >> 5;
    int lane  = threadIdx.x & 31;
    if (gwarp >= NPIX) return;
    const float4* xr = (const float4*)(x + (size_t)gwarp * CDIM);
    const float4* w4 = (const float4*)sw;
    float acc = 0.f;
#pragma unroll
    for (int i = 0; i < 4; i++) {
        float4 a = __ldg(xr + lane + 32*i);
        float4 b = __ldg(w4 + lane + 32*i);
        acc += a.x*b.x + a.y*b.y + a.z*b.z + a.w*b.w;
    }
#pragma unroll
    for (int o = 16; o; o >>= 1) acc += __shfl_xor_sync(0xffffffffu, acc, o);
    if (lane == 0) g_score[gwarp] = acc + sb[0];
}

// ---------------------------------------------------------------------------
// K2: per-window LayerNorm(25 scores) -> softmax -> weighted sum of 25
//     xr rows into g_xagg[win, 0:512].  One block (128 thr) per window.
// ---------------------------------------------------------------------------
__global__ void attn_agg_kernel(const float* __restrict__ x,
                                const float* __restrict__ lnw,
                                const float* __restrict__ lnb) {
    int win = blockIdx.x;
    int n   = win / (HH*WWN);
    int r   = win % (HH*WWN);
    int hh  = r / WWN, ww = r % WWN;

    __shared__ float s[25];
    __shared__ float wgt[25];
    int t = threadIdx.x;
    if (t < 25) {
        int ki = t / KW, kj = t % KW;
        s[t] = g_score[(n*HDIM + hh + ki)*WDIM + ww + kj];
    }
    __syncthreads();
    if (t == 0) {
        float mu = 0.f;
#pragma unroll
        for (int k = 0; k < 25; k++) mu += s[k];
        mu *= (1.f/25.f);
        float var = 0.f;
#pragma unroll
        for (int k = 0; k < 25; k++) { float d = s[k]-mu; var += d*d; }
        var *= (1.f/25.f);
        float inv = rsqrtf(var + LNEPS);
        float e[25];
        float mx = -1e30f;
#pragma unroll
        for (int k = 0; k < 25; k++) {
            float z = (s[k]-mu)*inv*lnw[k] + lnb[k];
            e[k] = z;
            mx = fmaxf(mx, z);
        }
        float sum = 0.f;
#pragma unroll
        for (int k = 0; k < 25; k++) { e[k] = __expf(e[k]-mx); sum += e[k]; }
        float rs = 1.f/sum;
#pragma unroll
        for (int k = 0; k < 25; k++) wgt[k] = e[k]*rs;
    }
    __syncthreads();

    // 128 threads x float4 = 512 channels
    float4 acc = make_float4(0.f,0.f,0.f,0.f);
#pragma unroll
    for (int ki = 0; ki < KW; ki++) {
        const float4* row0 = (const float4*)(x + ((size_t)((n*HDIM + hh + ki)*WDIM + ww)) * CDIM);
#pragma unroll
        for (int kj = 0; kj < KW; kj++) {
            float wk = wgt[ki*KW + kj];
            float4 v = __ldg(row0 + (size_t)kj*(CDIM/4) + t);
            acc.x += wk*v.x; acc.y += wk*v.y; acc.z += wk*v.z; acc.w += wk*v.w;
        }
    }
    ((float4*)g_xagg)[(size_t)win*(CDIM/4) + t] = acc;
}

// ---------------------------------------------------------------------------
// K3: out[n,o,hh,ww] = xagg[win,:] . proj_w[o,:] + proj_b[o]
//     M=6272 (= 49*128), N=512, K=512.  128x128x16 tiles, 8x8 microtile,
//     f32x2 packed FMA along M; contiguous float4 epilogue stores.
// ---------------------------------------------------------------------------
#define BM 128
#define BN 128
#define BK 16

__global__ __launch_bounds__(256, 2)
void gemm_kernel(const float* __restrict__ pw,
                 const float* __restrict__ pb,
                 float* __restrict__ out) {
    __shared__ float As[BK][BM];
    __shared__ float Bs[BK][BN];

    const int bm = blockIdx.x * BM;
    const int bn = blockIdx.y * BN;
    const int tid = threadIdx.x;
    const int tx = tid & 15;        // m group
    const int ty = tid >> 4;        // o group
    const int m_base = tx * 8;
    const int n_base = ty * 8;

    f2u acc[8][4];
#pragma unroll
    for (int j = 0; j < 8; j++)
#pragma unroll
        for (int i = 0; i < 4; i++) acc[j][i].u = 0ull;

    const int lrow = tid >> 2;          // 0..63
    const int lcol = (tid & 3) * 4;     // 0,4,8,12

    for (int k0 = 0; k0 < CDIM; k0 += BK) {
#pragma unroll
        for (int s = 0; s < 2; s++) {
            int row = lrow + s*64;
            float4 va = *(const float4*)(g_xagg + (size_t)(bm + row)*CDIM + k0 + lcol);
            As[lcol+0][row] = va.x; As[lcol+1][row] = va.y;
            As[lcol+2][row] = va.z; As[lcol+3][row] = va.w;
            float4 vb = *(const float4*)(pw + (size_t)(bn + row)*CDIM + k0 + lcol);
            Bs[lcol+0][row] = vb.x; Bs[lcol+1][row] = vb.y;
            Bs[lcol+2][row] = vb.z; Bs[lcol+3][row] = vb.w;
        }
        __syncthreads();

#pragma unroll
        for (int kk = 0; kk < BK; kk++) {
            f2u a2[4];
#pragma unroll
            for (int i = 0; i < 4; i++)
                a2[i].f = *(const float2*)&As[kk][m_base + 2*i];
            f2u bb[8];
#pragma unroll
            for (int j = 0; j < 8; j++) {
                float b = Bs[kk][n_base + j];
                bb[j].f = make_float2(b, b);
            }
#pragma unroll
            for (int j = 0; j < 8; j++)
#pragma unroll
                for (int i = 0; i < 4; i++)
                    fma_x2(acc[j][i], a2[i], bb[j]);
        }
        __syncthreads();
    }

    // epilogue: m -> (n_img, rem) ; rem..rem+7 contiguous in output for fixed o
    const int m0    = bm + m_base;           // multiple of 8, 784 % 8 == 0
    const int n_img = m0 / (HH*WWN);
    const int rem   = m0 % (HH*WWN);
#pragma unroll
    for (int j = 0; j < 8; j++) {
        int o = bn + n_base + j;
        float bias = __ldg(pb + o);
        float* dst = out + (size_t)n_img*(ODIM*HH*WWN) + (size_t)o*(HH*WWN) + rem;
        float4 v0 = make_float4(acc[j][0].f.x + bias, acc[j][0].f.y + bias,
                                acc[j][1].f.x + bias, acc[j][1].f.y + bias);
        float4 v1 = make_float4(acc[j][2].f.x + bias, acc[j][2].f.y + bias,
                                acc[j][3].f.x + bias, acc[j][3].f.y + bias);
        *(float4*)(dst)     = v0;
        *(float4*)(dst + 4) = v1;
    }
}

// ---------------------------------------------------------------------------
extern "C" void kernel_launch(void* const* d_in, const int* in_sizes, int n_in,
                              void* d_out, int out_size) {
    const float* x   = (const float*)d_in[0];
    const float* pw  = (const float*)d_in[1];
    const float* pb  = (const float*)d_in[2];
    const float* sw  = (const float*)d_in[3];
    const float* sb  = (const float*)d_in[4];
    const float* lnw = (const float*)d_in[5];
    const float* lnb = (const float*)d_in[6];
    float* out = (float*)d_out;

    // K1: one warp per pixel, 8192 warps
    score_kernel<<<(NPIX*32 + 255)/256, 256>>>(x, sw, sb);
    // K2: one block per window
    attn_agg_kernel<<<NWIN, 128>>>(x, lnw, lnb);
    // K3: GEMM 6272x512x512
    dim3 grid(NWIN/BM /* 49 */, ODIM/BN /* 4 */);
    gemm_kernel<<<grid, 256>>>(pw, pb, out);
}

// round 3
// speedup vs baseline: 1.8049x; 1.8049x over previous
#include <cuda_runtime.h>
#include <cuda_bf16.h>
#include <cstdint>

#define NIMG 8
#define CDIM 512
#define HDIM 32
#define WDIM 32
#define ODIM 512
#define KW   5
#define HH   28
#define WWN  28
#define NWIN (NIMG*HH*WWN)      // 6272
#define NPIX (NIMG*HDIM*WDIM)   // 8192
#define PIX_PER_IMG (HH*WWN)    // 784
#define LNEPS 1e-5f

// ---------------- scratch (no allocations allowed) ----------------
__device__ float g_score[NPIX];
__device__ __nv_bfloat16 g_xa_hi[(size_t)NWIN * CDIM];   // 6.4MB
__device__ __nv_bfloat16 g_xa_lo[(size_t)NWIN * CDIM];
__device__ __nv_bfloat16 g_pw_hi[ODIM * CDIM];
__device__ __nv_bfloat16 g_pw_lo[ODIM * CDIM];

__device__ __forceinline__ uint32_t s2u(const void* p) {
    return (uint32_t)__cvta_generic_to_shared(p);
}
__device__ __forceinline__ void ldmx4(uint32_t r[4], uint32_t a) {
    asm volatile("ldmatrix.sync.aligned.m8n8.x4.shared.b16 {%0,%1,%2,%3}, [%4];"
        : "=r"(r[0]), "=r"(r[1]), "=r"(r[2]), "=r"(r[3]) : "r"(a));
}
__device__ __forceinline__ void mma16816(float d[4], const uint32_t a[4], const uint32_t b[2]) {
    asm volatile("mma.sync.aligned.m16n8k16.row.col.f32.bf16.bf16.f32 "
        "{%0,%1,%2,%3}, {%4,%5,%6,%7}, {%8,%9}, {%0,%1,%2,%3};"
        : "+f"(d[0]), "+f"(d[1]), "+f"(d[2]), "+f"(d[3])
        : "r"(a[0]), "r"(a[1]), "r"(a[2]), "r"(a[3]), "r"(b[0]), "r"(b[1]));
}

// ---------------------------------------------------------------------------
// K1: score[p] = dot(xr[p,:], score_w) + score_b   (one warp per pixel)
// ---------------------------------------------------------------------------
__global__ void score_kernel(const float* __restrict__ x,
                             const float* __restrict__ sw,
                             const float* __restrict__ sb) {
    int gwarp = (blockIdx.x * blockDim.x + threadIdx.x) >> 5;
    int lane  = threadIdx.x & 31;
    if (gwarp >= NPIX) return;
    const float4* xr = (const float4*)(x + (size_t)gwarp * CDIM);
    const float4* w4 = (const float4*)sw;
    float acc = 0.f;
#pragma unroll
    for (int i = 0; i < 4; i++) {
        float4 a = __ldg(xr + lane + 32*i);
        float4 b = __ldg(w4 + lane + 32*i);
        acc += a.x*b.x + a.y*b.y + a.z*b.z + a.w*b.w;
    }
#pragma unroll
    for (int o = 16; o; o >>= 1) acc += __shfl_xor_sync(0xffffffffu, acc, o);
    if (lane == 0) g_score[gwarp] = acc + sb[0];
}

// ---------------------------------------------------------------------------
// prep: split proj_w into bf16 hi/lo
// ---------------------------------------------------------------------------
__global__ void prep_w_kernel(const float* __restrict__ pw) {
    int i = blockIdx.x * blockDim.x + threadIdx.x;
    float v = pw[i];
    __nv_bfloat16 h = __float2bfloat16(v);
    g_pw_hi[i] = h;
    g_pw_lo[i] = __float2bfloat16(v - __bfloat162float(h));
}

// ---------------------------------------------------------------------------
// K2: per-window LN(25 scores) -> softmax -> weighted sum of 25 xr rows,
//     written as bf16 hi/lo split.  One block (128 thr) per window.
// ---------------------------------------------------------------------------
__global__ void attn_agg_kernel(const float* __restrict__ x,
                                const float* __restrict__ lnw,
                                const float* __restrict__ lnb) {
    int win = blockIdx.x;
    int n   = win / (HH*WWN);
    int r   = win % (HH*WWN);
    int hh  = r / WWN, ww = r % WWN;

    __shared__ float s[25];
    __shared__ float wgt[25];
    int t = threadIdx.x;
    if (t < 25) {
        int ki = t / KW, kj = t % KW;
        s[t] = g_score[(n*HDIM + hh + ki)*WDIM + ww + kj];
    }
    __syncthreads();
    if (t == 0) {
        float mu = 0.f;
#pragma unroll
        for (int k = 0; k < 25; k++) mu += s[k];
        mu *= (1.f/25.f);
        float var = 0.f;
#pragma unroll
        for (int k = 0; k < 25; k++) { float d = s[k]-mu; var += d*d; }
        var *= (1.f/25.f);
        float inv = rsqrtf(var + LNEPS);
        float e[25];
        float mx = -1e30f;
#pragma unroll
        for (int k = 0; k < 25; k++) {
            float z = (s[k]-mu)*inv*lnw[k] + lnb[k];
            e[k] = z;
            mx = fmaxf(mx, z);
        }
        float sum = 0.f;
#pragma unroll
        for (int k = 0; k < 25; k++) { e[k] = __expf(e[k]-mx); sum += e[k]; }
        float rs = 1.f/sum;
#pragma unroll
        for (int k = 0; k < 25; k++) wgt[k] = e[k]*rs;
    }
    __syncthreads();

    float4 acc = make_float4(0.f,0.f,0.f,0.f);
#pragma unroll
    for (int ki = 0; ki < KW; ki++) {
        const float4* row0 = (const float4*)(x + ((size_t)((n*HDIM + hh + ki)*WDIM + ww)) * CDIM);
#pragma unroll
        for (int kj = 0; kj < KW; kj++) {
            float wk = wgt[ki*KW + kj];
            float4 v = __ldg(row0 + (size_t)kj*(CDIM/4) + t);
            acc.x += wk*v.x; acc.y += wk*v.y; acc.z += wk*v.z; acc.w += wk*v.w;
        }
    }
    size_t base = (size_t)win*CDIM + t*4;
    float v0 = acc.x, v1 = acc.y, v2 = acc.z, v3 = acc.w;
    __nv_bfloat16 h0 = __float2bfloat16(v0), h1 = __float2bfloat16(v1);
    __nv_bfloat16 h2 = __float2bfloat16(v2), h3 = __float2bfloat16(v3);
    __nv_bfloat162 H0; H0.x = h0; H0.y = h1;
    __nv_bfloat162 H1; H1.x = h2; H1.y = h3;
    __nv_bfloat162 L0, L1;
    L0.x = __float2bfloat16(v0 - __bfloat162float(h0));
    L0.y = __float2bfloat16(v1 - __bfloat162float(h1));
    L1.x = __float2bfloat16(v2 - __bfloat162float(h2));
    L1.y = __float2bfloat16(v3 - __bfloat162float(h3));
    *(__nv_bfloat162*)(g_xa_hi + base)     = H0;
    *(__nv_bfloat162*)(g_xa_hi + base + 2) = H1;
    *(__nv_bfloat162*)(g_xa_lo + base)     = L0;
    *(__nv_bfloat162*)(g_xa_lo + base + 2) = L1;
}

// ---------------------------------------------------------------------------
// K3: HMMA (mma.sync m16n8k16 bf16) GEMM with bf16x3 split.
//     M=6272, N=512, K=512. CTA 128x128, K-chunk 32 (hi|lo packed in 128B rows,
//     SW128 swizzle), 8 warps (2x4), warp tile 64x32, reg-prefetch double buffer.
// ---------------------------------------------------------------------------
#define KCH 32
#define NCH (CDIM/KCH)            // 16
#define ATILE_B (128*128)         // 16KB: 128 rows x (32 hi | 32 lo) bf16
#define STAGE_B (2*ATILE_B)       // 32KB (A tile + B tile)
#define EPI_B   (128*129*4)       // 66048
#define DSMEM_B EPI_B             // >= 2*STAGE_B (65536)

__global__ __launch_bounds__(256)
void hmma_gemm_kernel(const float* __restrict__ pb, float* __restrict__ out) {
    extern __shared__ char dsm[];
    const int tid = threadIdx.x, wid = tid >> 5, lane = tid & 31;
    const int bm = blockIdx.x * 128, bn = blockIdx.y * 128;
    const int m_org = (wid & 1) * 64;
    const int n_org = (wid >> 1) * 32;
    const int quad = lane >> 3, rq = lane & 7;

    float acc[4][4][4];
#pragma unroll
    for (int a = 0; a < 4; a++)
#pragma unroll
        for (int b = 0; b < 4; b++)
#pragma unroll
            for (int c = 0; c < 4; c++) acc[a][b][c] = 0.f;

    uint4 rg[8];
    // per-thread staging coords: idx = tid + i*256 -> (tile, row, j16)
    auto LDG_CHUNK = [&](int ck) {
        const int k0 = ck * KCH;
#pragma unroll
        for (int i = 0; i < 8; i++) {
            int idx = tid + i*256;
            int tile = idx >> 10, c = idx & 1023, r = c >> 3, j = c & 7;
            int col = k0 + (j & 3) * 8;
            const __nv_bfloat16* src;
            if (tile == 0) src = (j < 4 ? g_xa_hi : g_xa_lo) + (size_t)(bm + r)*CDIM + col;
            else           src = (j < 4 ? g_pw_hi : g_pw_lo) + (size_t)(bn + r)*CDIM + col;
            rg[i] = *(const uint4*)src;
        }
    };
    auto STS_CHUNK = [&](char* buf) {
#pragma unroll
        for (int i = 0; i < 8; i++) {
            int idx = tid + i*256;
            int tile = idx >> 10, c = idx & 1023, r = c >> 3, j = c & 7;
            uint32_t off = (uint32_t)(r*128 + j*16);
            off ^= (off >> 3) & 0x70;
            *(uint4*)(buf + tile*ATILE_B + off) = rg[i];
        }
    };

    LDG_CHUNK(0);
    for (int ck = 0; ck < NCH; ck++) {
        char* buf = dsm + (ck & 1) * STAGE_B;
        STS_CHUNK(buf);
        __syncthreads();
        if (ck + 1 < NCH) LDG_CHUNK(ck + 1);

        const uint32_t abase = s2u(buf);
        const uint32_t bbase = s2u(buf + ATILE_B);
#pragma unroll
        for (int ks = 0; ks < 2; ks++) {
            const int jA = ks * 2;
            uint32_t ah[4][4], al[4][4];
#pragma unroll
            for (int mi = 0; mi < 4; mi++) {
                int row = m_org + mi*16 + rq + ((quad & 1) << 3);
                int jh = jA + (quad >> 1);
                uint32_t o1 = (uint32_t)(row*128 + jh*16);      o1 ^= (o1 >> 3) & 0x70;
                uint32_t o2 = (uint32_t)(row*128 + (jh+4)*16);  o2 ^= (o2 >> 3) & 0x70;
                ldmx4(ah[mi], abase + o1);
                ldmx4(al[mi], abase + o2);
            }
            uint32_t bh[2][4], bl[2][4];
#pragma unroll
            for (int nb = 0; nb < 2; nb++) {
                int row = n_org + nb*16 + rq + ((quad >> 1) << 3);
                int jh = jA + (quad & 1);
                uint32_t o1 = (uint32_t)(row*128 + jh*16);      o1 ^= (o1 >> 3) & 0x70;
                uint32_t o2 = (uint32_t)(row*128 + (jh+4)*16);  o2 ^= (o2 >> 3) & 0x70;
                ldmx4(bh[nb], bbase + o1);
                ldmx4(bl[nb], bbase + o2);
            }
#pragma unroll
            for (int mi = 0; mi < 4; mi++)
#pragma unroll
                for (int nj = 0; nj < 4; nj++) {
                    const uint32_t* Bh = &bh[nj >> 1][(nj & 1) * 2];
                    const uint32_t* Bl = &bl[nj >> 1][(nj & 1) * 2];
                    mma16816(acc[mi][nj], ah[mi], Bh);
                    mma16816(acc[mi][nj], ah[mi], Bl);
                    mma16816(acc[mi][nj], al[mi], Bh);
                }
        }
        __syncthreads();
    }

    // epilogue: transpose through smem for coalesced (o-major) global stores
    float* cs = (float*)dsm;
#pragma unroll
    for (int mi = 0; mi < 4; mi++)
#pragma unroll
        for (int nj = 0; nj < 4; nj++) {
            int row = m_org + mi*16 + (lane >> 2);
            int col = n_org + nj*8 + 2*(lane & 3);
            cs[row*129 + col]       = acc[mi][nj][0];
            cs[row*129 + col + 1]   = acc[mi][nj][1];
            cs[(row+8)*129 + col]   = acc[mi][nj][2];
            cs[(row+8)*129 + col+1] = acc[mi][nj][3];
        }
    __syncthreads();
#pragma unroll 4
    for (int it = 0; it < 64; it++) {
        int linear = it*256 + tid;
        int col = linear >> 7, row = linear & 127;
        int m = bm + row, o = bn + col;
        int nimg = m / PIX_PER_IMG;
        int rem  = m - nimg * PIX_PER_IMG;
        out[(size_t)nimg*ODIM*PIX_PER_IMG + (size_t)o*PIX_PER_IMG + rem] =
            cs[row*129 + col] + __ldg(pb + o);
    }
}

// ---------------------------------------------------------------------------
extern "C" void kernel_launch(void* const* d_in, const int* in_sizes, int n_in,
                              void* d_out, int out_size) {
    const float* x   = (const float*)d_in[0];
    const float* pw  = (const float*)d_in[1];
    const float* pb  = (const float*)d_in[2];
    const float* sw  = (const float*)d_in[3];
    const float* sb  = (const float*)d_in[4];
    const float* lnw = (const float*)d_in[5];
    const float* lnb = (const float*)d_in[6];
    float* out = (float*)d_out;

    cudaFuncSetAttribute(hmma_gemm_kernel,
                         cudaFuncAttributeMaxDynamicSharedMemorySize, DSMEM_B);

    score_kernel<<<(NPIX*32 + 255)/256, 256>>>(x, sw, sb);
    prep_w_kernel<<<(ODIM*CDIM)/256, 256>>>(pw);
    attn_agg_kernel<<<NWIN, 128>>>(x, lnw, lnb);
    dim3 grid(NWIN/128 /*49*/, ODIM/128 /*4*/);
    hmma_gemm_kernel<<<grid, 256, DSMEM_B>>>(pb, out);
}

// round 4
// speedup vs baseline: 2.3683x; 1.3121x over previous
#include <cuda_runtime.h>
#include <cuda_bf16.h>
#include <cstdint>

#define NIMG 8
#define CDIM 512
#define HDIM 32
#define WDIM 32
#define ODIM 512
#define KW   5
#define HH   28
#define WWN  28
#define NWIN (NIMG*HH*WWN)      // 6272
#define NPIX (NIMG*HDIM*WDIM)   // 8192
#define PIX_PER_IMG (HH*WWN)    // 784
#define LNEPS 1e-5f

// ---------------- scratch (no allocations allowed) ----------------
__device__ float g_score[NPIX];
__device__ __nv_bfloat16 g_xa_hi[(size_t)NWIN * CDIM];
__device__ __nv_bfloat16 g_xa_lo[(size_t)NWIN * CDIM];
__device__ __nv_bfloat16 g_pw_hi[ODIM * CDIM];
__device__ __nv_bfloat16 g_pw_lo[ODIM * CDIM];

__device__ __forceinline__ uint32_t s2u(const void* p) {
    return (uint32_t)__cvta_generic_to_shared(p);
}
__device__ __forceinline__ void ldmx4(uint32_t r[4], uint32_t a) {
    asm volatile("ldmatrix.sync.aligned.m8n8.x4.shared.b16 {%0,%1,%2,%3}, [%4];"
        : "=r"(r[0]), "=r"(r[1]), "=r"(r[2]), "=r"(r[3]) : "r"(a));
}
__device__ __forceinline__ void mma16816(float d[4], const uint32_t a[4], const uint32_t b[2]) {
    asm volatile("mma.sync.aligned.m16n8k16.row.col.f32.bf16.bf16.f32 "
        "{%0,%1,%2,%3}, {%4,%5,%6,%7}, {%8,%9}, {%0,%1,%2,%3};"
        : "+f"(d[0]), "+f"(d[1]), "+f"(d[2]), "+f"(d[3])
        : "r"(a[0]), "r"(a[1]), "r"(a[2]), "r"(a[3]), "r"(b[0]), "r"(b[1]));
}
__device__ __forceinline__ void cpasync16(uint32_t s, const void* g) {
    asm volatile("cp.async.cg.shared.global [%0], [%1], 16;" :: "r"(s), "l"(g));
}
#define CP_COMMIT() asm volatile("cp.async.commit_group;" ::: "memory")
#define CP_WAIT1()  asm volatile("cp.async.wait_group 1;" ::: "memory")

// ---------------------------------------------------------------------------
// K1 (fused): blocks [0,1024): score GEMV; blocks [1024,2048): proj_w hi/lo split
// ---------------------------------------------------------------------------
__global__ void score_prep_kernel(const float* __restrict__ x,
                                  const float* __restrict__ sw,
                                  const float* __restrict__ sb,
                                  const float* __restrict__ pw) {
    if (blockIdx.x >= 1024) {
        int i = (blockIdx.x - 1024) * 256 + threadIdx.x;   // < 262144
        float v = pw[i];
        __nv_bfloat16 h = __float2bfloat16(v);
        g_pw_hi[i] = h;
        g_pw_lo[i] = __float2bfloat16(v - __bfloat162float(h));
        return;
    }
    int gwarp = (blockIdx.x * blockDim.x + threadIdx.x) >> 5;
    int lane  = threadIdx.x & 31;
    const float4* xr = (const float4*)(x + (size_t)gwarp * CDIM);
    const float4* w4 = (const float4*)sw;
    float acc = 0.f;
#pragma unroll
    for (int i = 0; i < 4; i++) {
        float4 a = __ldg(xr + lane + 32*i);
        float4 b = __ldg(w4 + lane + 32*i);
        acc += a.x*b.x + a.y*b.y + a.z*b.z + a.w*b.w;
    }
#pragma unroll
    for (int o = 16; o; o >>= 1) acc += __shfl_xor_sync(0xffffffffu, acc, o);
    if (lane == 0) g_score[gwarp] = acc + sb[0];
}

// ---------------------------------------------------------------------------
// K2: 7 windows per block (one 5x11 patch). LN+softmax per window, then
//     stream 55 pixel-rows once, accumulating all 7 windows. bf16 hi/lo out.
// ---------------------------------------------------------------------------
__global__ __launch_bounds__(128)
void attn_agg_kernel(const float* __restrict__ x,
                     const float* __restrict__ lnw,
                     const float* __restrict__ lnb) {
    const int b = blockIdx.x;            // NIMG*HH*4 = 896
    const int n  = b / (HH*4);
    const int r  = b % (HH*4);
    const int hh = r >> 2;
    const int ww0 = (r & 3) * 7;
    const int t = threadIdx.x;

    __shared__ float s[5][11];
    __shared__ float wgt[7][25];
    if (t < 55) {
        int ki = t / 11, kj = t % 11;
        s[ki][kj] = g_score[(n*HDIM + hh + ki)*WDIM + ww0 + kj];
    }
    __syncthreads();
    if (t < 7) {
        float sc[25];
#pragma unroll
        for (int ki = 0; ki < 5; ki++)
#pragma unroll
            for (int kj = 0; kj < 5; kj++) sc[ki*5+kj] = s[ki][t+kj];
        float mu = 0.f;
#pragma unroll
        for (int k = 0; k < 25; k++) mu += sc[k];
        mu *= (1.f/25.f);
        float var = 0.f;
#pragma unroll
        for (int k = 0; k < 25; k++) { float d = sc[k]-mu; var += d*d; }
        var *= (1.f/25.f);
        float inv = rsqrtf(var + LNEPS);
        float e[25], mx = -1e30f;
#pragma unroll
        for (int k = 0; k < 25; k++) {
            float z = (sc[k]-mu)*inv*lnw[k] + lnb[k];
            e[k] = z; mx = fmaxf(mx, z);
        }
        float sum = 0.f;
#pragma unroll
        for (int k = 0; k < 25; k++) { e[k] = __expf(e[k]-mx); sum += e[k]; }
        float rs = 1.f/sum;
#pragma unroll
        for (int k = 0; k < 25; k++) wgt[t][k] = e[k]*rs;
    }
    __syncthreads();

    float4 acc[7];
#pragma unroll
    for (int w = 0; w < 7; w++) acc[w] = make_float4(0.f,0.f,0.f,0.f);

#pragma unroll
    for (int ki = 0; ki < 5; ki++) {
        const float4* rb = (const float4*)(x +
            ((size_t)((n*HDIM + hh + ki)*WDIM + ww0)) * CDIM) + t;
#pragma unroll
        for (int kj = 0; kj < 11; kj++) {
            float4 v = __ldg(rb + kj*(CDIM/4));
#pragma unroll
            for (int w = 0; w < 7; w++) {
                if (w <= kj && kj - w <= 4) {
                    float wk = wgt[w][ki*5 + (kj - w)];
                    acc[w].x += wk*v.x; acc[w].y += wk*v.y;
                    acc[w].z += wk*v.z; acc[w].w += wk*v.w;
                }
            }
        }
    }

    const int win0 = (n*HH + hh)*WWN + ww0;
#pragma unroll
    for (int w = 0; w < 7; w++) {
        size_t base = (size_t)(win0 + w)*CDIM + t*4;
        float v0 = acc[w].x, v1 = acc[w].y, v2 = acc[w].z, v3 = acc[w].w;
        __nv_bfloat16 h0 = __float2bfloat16(v0), h1 = __float2bfloat16(v1);
        __nv_bfloat16 h2 = __float2bfloat16(v2), h3 = __float2bfloat16(v3);
        __nv_bfloat162 H0; H0.x = h0; H0.y = h1;
        __nv_bfloat162 H1; H1.x = h2; H1.y = h3;
        __nv_bfloat162 L0, L1;
        L0.x = __float2bfloat16(v0 - __bfloat162float(h0));
        L0.y = __float2bfloat16(v1 - __bfloat162float(h1));
        L1.x = __float2bfloat16(v2 - __bfloat162float(h2));
        L1.y = __float2bfloat16(v3 - __bfloat162float(h3));
        *(__nv_bfloat162*)(g_xa_hi + base)     = H0;
        *(__nv_bfloat162*)(g_xa_hi + base + 2) = H1;
        *(__nv_bfloat162*)(g_xa_lo + base)     = L0;
        *(__nv_bfloat162*)(g_xa_lo + base + 2) = L1;
    }
}

// ---------------------------------------------------------------------------
// K3: HMMA bf16x3 GEMM. CTA 128x128, KCH=32 (hi|lo packed, SW128 swizzle),
//     cp.async 3-stage pipeline, 8 warps (64x32 warp tile), 2 CTAs/SM.
// ---------------------------------------------------------------------------
#define KCH 32
#define NCH (CDIM/KCH)            // 16
#define ATILE_B (128*128)         // 16KB
#define STAGE_B (2*ATILE_B)       // 32KB
#define NSTG 3
#define DSMEM_B (NSTG*STAGE_B)    // 98304 >= epi 66048

__global__ __launch_bounds__(256, 2)
void hmma_gemm_kernel(const float* __restrict__ pb, float* __restrict__ out) {
    extern __shared__ char dsm[];
    const int tid = threadIdx.x, wid = tid >> 5, lane = tid & 31;
    const int bm = blockIdx.x * 128, bn = blockIdx.y * 128;
    const int m_org = (wid & 1) * 64;
    const int n_org = (wid >> 1) * 32;
    const int quad = lane >> 3, rq = lane & 7;

    float acc[4][4][4];
#pragma unroll
    for (int a = 0; a < 4; a++)
#pragma unroll
        for (int b = 0; b < 4; b++)
#pragma unroll
            for (int c = 0; c < 4; c++) acc[a][b][c] = 0.f;

    auto ISSUE = [&](int ck) {
        if (ck < NCH) {
            const int k0 = ck * KCH;
            char* buf = dsm + (ck % NSTG) * STAGE_B;
#pragma unroll
            for (int i = 0; i < 8; i++) {
                int idx = tid + i*256;
                int tile = idx >> 10, c = idx & 1023, r = c >> 3, j = c & 7;
                int col = k0 + (j & 3) * 8;
                const __nv_bfloat16* src;
                if (tile == 0) src = (j < 4 ? g_xa_hi : g_xa_lo) + (size_t)(bm + r)*CDIM + col;
                else           src = (j < 4 ? g_pw_hi : g_pw_lo) + (size_t)(bn + r)*CDIM + col;
                uint32_t off = (uint32_t)(r*128 + j*16);
                off ^= (off >> 3) & 0x70;
                cpasync16(s2u(buf + tile*ATILE_B + off), src);
            }
        }
        CP_COMMIT();   // empty groups at the tail keep wait_group accounting simple
    };

    ISSUE(0);
    ISSUE(1);
    for (int ck = 0; ck < NCH; ck++) {
        char* buf = dsm + (ck % NSTG) * STAGE_B;
        CP_WAIT1();
        __syncthreads();
        ISSUE(ck + 2);

        const uint32_t abase = s2u(buf);
        const uint32_t bbase = s2u(buf + ATILE_B);
#pragma unroll
        for (int ks = 0; ks < 2; ks++) {
            const int jA = ks * 2;
            // hi fragments of A, hi+lo of B
            uint32_t ah[4][4];
#pragma unroll
            for (int mi = 0; mi < 4; mi++) {
                int row = m_org + mi*16 + rq + ((quad & 1) << 3);
                int jh = jA + (quad >> 1);
                uint32_t o1 = (uint32_t)(row*128 + jh*16); o1 ^= (o1 >> 3) & 0x70;
                ldmx4(ah[mi], abase + o1);
            }
            uint32_t bh[2][4], bl[2][4];
#pragma unroll
            for (int nb = 0; nb < 2; nb++) {
                int row = n_org + nb*16 + rq + ((quad >> 1) << 3);
                int jh = jA + (quad & 1);
                uint32_t o1 = (uint32_t)(row*128 + jh*16);     o1 ^= (o1 >> 3) & 0x70;
                uint32_t o2 = (uint32_t)(row*128 + (jh+4)*16); o2 ^= (o2 >> 3) & 0x70;
                ldmx4(bh[nb], bbase + o1);
                ldmx4(bl[nb], bbase + o2);
            }
#pragma unroll
            for (int mi = 0; mi < 4; mi++)
#pragma unroll
                for (int nj = 0; nj < 4; nj++) {
                    const uint32_t* Bh = &bh[nj >> 1][(nj & 1) * 2];
                    const uint32_t* Bl = &bl[nj >> 1][(nj & 1) * 2];
                    mma16816(acc[mi][nj], ah[mi], Bh);
                    mma16816(acc[mi][nj], ah[mi], Bl);
                }
            // lo fragments of A reuse ah's registers (ah dead after loop above)
            uint32_t al[4][4];
#pragma unroll
            for (int mi = 0; mi < 4; mi++) {
                int row = m_org + mi*16 + rq + ((quad & 1) << 3);
                int jh = jA + (quad >> 1) + 4;
                uint32_t o2 = (uint32_t)(row*128 + jh*16); o2 ^= (o2 >> 3) & 0x70;
                ldmx4(al[mi], abase + o2);
            }
#pragma unroll
            for (int mi = 0; mi < 4; mi++)
#pragma unroll
                for (int nj = 0; nj < 4; nj++) {
                    const uint32_t* Bh = &bh[nj >> 1][(nj & 1) * 2];
                    mma16816(acc[mi][nj], al[mi], Bh);
                }
        }
        __syncthreads();
    }

    // epilogue: transpose through smem for coalesced (o-major) global stores
    float* cs = (float*)dsm;
#pragma unroll
    for (int mi = 0; mi < 4; mi++)
#pragma unroll
        for (int nj = 0; nj < 4; nj++) {
            int row = m_org + mi*16 + (lane >> 2);
            int col = n_org + nj*8 + 2*(lane & 3);
            cs[row*129 + col]       = acc[mi][nj][0];
            cs[row*129 + col + 1]   = acc[mi][nj][1];
            cs[(row+8)*129 + col]   = acc[mi][nj][2];
            cs[(row+8)*129 + col+1] = acc[mi][nj][3];
        }
    __syncthreads();
#pragma unroll 4
    for (int it = 0; it < 64; it++) {
        int linear = it*256 + tid;
        int col = linear >> 7, row = linear & 127;
        int m = bm + row, o = bn + col;
        int nimg = m / PIX_PER_IMG;
        int rem  = m - nimg * PIX_PER_IMG;
        out[(size_t)nimg*ODIM*PIX_PER_IMG + (size_t)o*PIX_PER_IMG + rem] =
            cs[row*129 + col] + __ldg(pb + o);
    }
}

// ---------------------------------------------------------------------------
extern "C" void kernel_launch(void* const* d_in, const int* in_sizes, int n_in,
                              void* d_out, int out_size) {
    const float* x   = (const float*)d_in[0];
    const float* pw  = (const float*)d_in[1];
    const float* pb  = (const float*)d_in[2];
    const float* sw  = (const float*)d_in[3];
    const float* sb  = (const float*)d_in[4];
    const float* lnw = (const float*)d_in[5];
    const float* lnb = (const float*)d_in[6];
    float* out = (float*)d_out;

    cudaFuncSetAttribute(hmma_gemm_kernel,
                         cudaFuncAttributeMaxDynamicSharedMemorySize, DSMEM_B);

    score_prep_kernel<<<2048, 256>>>(x, sw, sb, pw);
    attn_agg_kernel<<<NIMG*HH*4, 128>>>(x, lnw, lnb);
    dim3 grid(NWIN/128 /*49*/, ODIM/128 /*4*/);
    hmma_gemm_kernel<<<grid, 256, DSMEM_B>>>(pb, out);
}

// round 5
// speedup vs baseline: 3.6201x; 1.5286x over previous
#include <cuda_runtime.h>
#include <cuda_fp16.h>
#include <cuda_bf16.h>
#include <cstdint>

#define NIMG 8
#define CDIM 512
#define HDIM 32
#define WDIM 32
#define ODIM 512
#define KW   5
#define HH   28
#define WWN  28
#define NWIN (NIMG*HH*WWN)      // 6272
#define NPIX (NIMG*HDIM*WDIM)   // 8192
#define PIX_PER_IMG (HH*WWN)    // 784
#define LNEPS 1e-5f

// ---------------- scratch (no allocations allowed) ----------------
__device__ float g_score[NPIX];
__device__ __half g_xa_h[(size_t)NWIN * CDIM];   // 6.4MB (fp16 aggregate)
__device__ __half g_pw_hi[ODIM * CDIM];
__device__ __half g_pw_lo[ODIM * CDIM];

__device__ __forceinline__ uint32_t s2u(const void* p) {
    return (uint32_t)__cvta_generic_to_shared(p);
}
__device__ __forceinline__ void ldmx4(uint32_t r[4], uint32_t a) {
    asm volatile("ldmatrix.sync.aligned.m8n8.x4.shared.b16 {%0,%1,%2,%3}, [%4];"
        : "=r"(r[0]), "=r"(r[1]), "=r"(r[2]), "=r"(r[3]) : "r"(a));
}
__device__ __forceinline__ void mma16816(float d[4], const uint32_t a[4], const uint32_t b[2]) {
    asm volatile("mma.sync.aligned.m16n8k16.row.col.f32.f16.f16.f32 "
        "{%0,%1,%2,%3}, {%4,%5,%6,%7}, {%8,%9}, {%0,%1,%2,%3};"
        : "+f"(d[0]), "+f"(d[1]), "+f"(d[2]), "+f"(d[3])
        : "r"(a[0]), "r"(a[1]), "r"(a[2]), "r"(a[3]), "r"(b[0]), "r"(b[1]));
}
__device__ __forceinline__ void cpasync16(uint32_t s, const void* g) {
    asm volatile("cp.async.cg.shared.global [%0], [%1], 16;" :: "r"(s), "l"(g));
}
#define CP_COMMIT() asm volatile("cp.async.commit_group;" ::: "memory")
#define CP_WAIT1()  asm volatile("cp.async.wait_group 1;" ::: "memory")

// ---------------------------------------------------------------------------
// K1 (fused): blocks [0,512): score GEMV, 2 pixels per warp (MLP=12/thread);
//             blocks [512,1536): proj_w fp16 hi/lo split
// ---------------------------------------------------------------------------
__global__ void score_prep_kernel(const float* __restrict__ x,
                                  const float* __restrict__ sw,
                                  const float* __restrict__ sb,
                                  const float* __restrict__ pw) {
    if (blockIdx.x >= 512) {
        int i = (blockIdx.x - 512) * 256 + threadIdx.x;   // < 262144
        float v = pw[i];
        __half h = __float2half(v);
        g_pw_hi[i] = h;
        g_pw_lo[i] = __float2half(v - __half2float(h));
        return;
    }
    int gw   = blockIdx.x * 8 + (threadIdx.x >> 5);  // 0..4095
    int lane = threadIdx.x & 31;
    int p0 = gw * 2;
    const float4* x0 = (const float4*)(x + (size_t)p0 * CDIM);
    const float4* x1 = x0 + CDIM/4;
    const float4* w4 = (const float4*)sw;
    float a0 = 0.f, a1 = 0.f;
#pragma unroll
    for (int i = 0; i < 4; i++) {
        float4 va = __ldg(x0 + lane + 32*i);
        float4 vb = __ldg(x1 + lane + 32*i);
        float4 vw = __ldg(w4 + lane + 32*i);
        a0 += va.x*vw.x + va.y*vw.y + va.z*vw.z + va.w*vw.w;
        a1 += vb.x*vw.x + vb.y*vw.y + vb.z*vw.z + vb.w*vw.w;
    }
#pragma unroll
    for (int o = 16; o; o >>= 1) {
        a0 += __shfl_xor_sync(0xffffffffu, a0, o);
        a1 += __shfl_xor_sync(0xffffffffu, a1, o);
    }
    if (lane == 0) {
        float b = sb[0];
        g_score[p0]   = a0 + b;
        g_score[p0+1] = a1 + b;
    }
}

// ---------------------------------------------------------------------------
// K2: 7 windows per block (one 5x11 patch). LN+softmax per window, then
//     stream 55 pixel-rows once, accumulating all 7 windows. fp16 out.
// ---------------------------------------------------------------------------
__global__ __launch_bounds__(128)
void attn_agg_kernel(const float* __restrict__ x,
                     const float* __restrict__ lnw,
                     const float* __restrict__ lnb) {
    const int b = blockIdx.x;            // NIMG*HH*4 = 896
    const int n  = b / (HH*4);
    const int r  = b % (HH*4);
    const int hh = r >> 2;
    const int ww0 = (r & 3) * 7;
    const int t = threadIdx.x;

    __shared__ float s[5][11];
    __shared__ float wgt[7][25];
    if (t < 55) {
        int ki = t / 11, kj = t % 11;
        s[ki][kj] = g_score[(n*HDIM + hh + ki)*WDIM + ww0 + kj];
    }
    __syncthreads();
    if (t < 7) {
        float sc[25];
#pragma unroll
        for (int ki = 0; ki < 5; ki++)
#pragma unroll
            for (int kj = 0; kj < 5; kj++) sc[ki*5+kj] = s[ki][t+kj];
        float mu = 0.f;
#pragma unroll
        for (int k = 0; k < 25; k++) mu += sc[k];
        mu *= (1.f/25.f);
        float var = 0.f;
#pragma unroll
        for (int k = 0; k < 25; k++) { float d = sc[k]-mu; var += d*d; }
        var *= (1.f/25.f);
        float inv = rsqrtf(var + LNEPS);
        float e[25], mx = -1e30f;
#pragma unroll
        for (int k = 0; k < 25; k++) {
            float z = (sc[k]-mu)*inv*lnw[k] + lnb[k];
            e[k] = z; mx = fmaxf(mx, z);
        }
        float sum = 0.f;
#pragma unroll
        for (int k = 0; k < 25; k++) { e[k] = __expf(e[k]-mx); sum += e[k]; }
        float rs = 1.f/sum;
#pragma unroll
        for (int k = 0; k < 25; k++) wgt[t][k] = e[k]*rs;
    }
    __syncthreads();

    float4 acc[7];
#pragma unroll
    for (int w = 0; w < 7; w++) acc[w] = make_float4(0.f,0.f,0.f,0.f);

#pragma unroll
    for (int ki = 0; ki < 5; ki++) {
        const float4* rb = (const float4*)(x +
            ((size_t)((n*HDIM + hh + ki)*WDIM + ww0)) * CDIM) + t;
#pragma unroll
        for (int kj = 0; kj < 11; kj++) {
            float4 v = __ldg(rb + kj*(CDIM/4));
#pragma unroll
            for (int w = 0; w < 7; w++) {
                if (w <= kj && kj - w <= 4) {
                    float wk = wgt[w][ki*5 + (kj - w)];
                    acc[w].x += wk*v.x; acc[w].y += wk*v.y;
                    acc[w].z += wk*v.z; acc[w].w += wk*v.w;
                }
            }
        }
    }

    const int win0 = (n*HH + hh)*WWN + ww0;
#pragma unroll
    for (int w = 0; w < 7; w++) {
        size_t base = (size_t)(win0 + w)*CDIM + t*4;
        __half2 H0; H0.x = __float2half(acc[w].x); H0.y = __float2half(acc[w].y);
        __half2 H1; H1.x = __float2half(acc[w].z); H1.y = __float2half(acc[w].w);
        *(__half2*)(g_xa_h + base)     = H0;
        *(__half2*)(g_xa_h + base + 2) = H1;
    }
}

// ---------------------------------------------------------------------------
// K3: HMMA fp16x2 GEMM. out = A_h * (B_h + B_l). CTA 128x64, KCH=64,
//     SW128 swizzle, 3-stage cp.async, 8 warps (32x32 warp tile), 2 CTA/SM.
// ---------------------------------------------------------------------------
#define BM 128
#define BN 64
#define KCH 64
#define NCH (CDIM/KCH)            // 8
#define ATILE_B (BM*128)          // 16384: 128 rows x 64 fp16 (128B rows)
#define BTILE_B (BN*128)          // 8192
#define STAGE_B (ATILE_B + 2*BTILE_B)   // 32768
#define NSTG 3
#define DSMEM_B (NSTG*STAGE_B)    // 98304 >= epi 33280

__global__ __launch_bounds__(256, 2)
void hmma_gemm_kernel(const float* __restrict__ pb, float* __restrict__ out) {
    extern __shared__ char dsm[];
    const int tid = threadIdx.x, wid = tid >> 5, lane = tid & 31;
    const int bm = blockIdx.x * BM, bn = blockIdx.y * BN;
    const int m_org = (wid & 3) * 32;
    const int n_org = (wid >> 2) * 32;
    const int quad = lane >> 3, rq = lane & 7;

    float acc[2][4][4];
#pragma unroll
    for (int a = 0; a < 2; a++)
#pragma unroll
        for (int b = 0; b < 4; b++)
#pragma unroll
            for (int c = 0; c < 4; c++) acc[a][b][c] = 0.f;

    auto ISSUE = [&](int ck) {
        if (ck < NCH) {
            const int k0 = ck * KCH;
            char* buf = dsm + (ck % NSTG) * STAGE_B;
#pragma unroll
            for (int i = 0; i < 8; i++) {
                int idx = tid + i*256;             // 0..2047
                if (idx < 1024) {                  // A: 128 rows x 8 chunks
                    int r = idx >> 3, j = idx & 7;
                    uint32_t off = (uint32_t)(r*128 + j*16);
                    off ^= (off >> 3) & 0x70;
                    cpasync16(s2u(buf + off),
                              g_xa_h + (size_t)(bm + r)*CDIM + k0 + j*8);
                } else {                           // B hi/lo: 64 rows x 8 chunks each
                    int t2 = idx - 1024;
                    int half = t2 >> 9;            // 0=hi, 1=lo
                    int c = t2 & 511, r = c >> 3, j = c & 7;
                    uint32_t off = (uint32_t)(r*128 + j*16);
                    off ^= (off >> 3) & 0x70;
                    const __half* src = (half ? g_pw_lo : g_pw_hi)
                                        + (size_t)(bn + r)*CDIM + k0 + j*8;
                    cpasync16(s2u(buf + ATILE_B + half*BTILE_B + off), src);
                }
            }
        }
        CP_COMMIT();
    };

    ISSUE(0);
    ISSUE(1);
    for (int ck = 0; ck < NCH; ck++) {
        char* buf = dsm + (ck % NSTG) * STAGE_B;
        CP_WAIT1();
        __syncthreads();
        ISSUE(ck + 2);

        const uint32_t abase = s2u(buf);
        const uint32_t hbase = s2u(buf + ATILE_B);
        const uint32_t lbase = s2u(buf + ATILE_B + BTILE_B);
#pragma unroll
        for (int ks = 0; ks < 4; ks++) {
            const int jA = ks * 2;
            uint32_t ah[2][4];
#pragma unroll
            for (int mi = 0; mi < 2; mi++) {
                int row = m_org + mi*16 + rq + ((quad & 1) << 3);
                int jh = jA + (quad >> 1);
                uint32_t o = (uint32_t)(row*128 + jh*16); o ^= (o >> 3) & 0x70;
                ldmx4(ah[mi], abase + o);
            }
            uint32_t bh[2][4], bl[2][4];
#pragma unroll
            for (int nb = 0; nb < 2; nb++) {
                int row = n_org + nb*16 + rq + ((quad >> 1) << 3);
                int jh = jA + (quad & 1);
                uint32_t o = (uint32_t)(row*128 + jh*16); o ^= (o >> 3) & 0x70;
                ldmx4(bh[nb], hbase + o);
                ldmx4(bl[nb], lbase + o);
            }
#pragma unroll
            for (int mi = 0; mi < 2; mi++)
#pragma unroll
                for (int nj = 0; nj < 4; nj++) {
                    const uint32_t* Bh = &bh[nj >> 1][(nj & 1) * 2];
                    const uint32_t* Bl = &bl[nj >> 1][(nj & 1) * 2];
                    mma16816(acc[mi][nj], ah[mi], Bh);
                    mma16816(acc[mi][nj], ah[mi], Bl);
                }
        }
        __syncthreads();
    }

    // epilogue: transpose through smem for coalesced (o-major) global stores
    float* cs = (float*)dsm;
#pragma unroll
    for (int mi = 0; mi < 2; mi++)
#pragma unroll
        for (int nj = 0; nj < 4; nj++) {
            int row = m_org + mi*16 + (lane >> 2);
            int col = n_org + nj*8 + 2*(lane & 3);
            cs[row*65 + col]       = acc[mi][nj][0];
            cs[row*65 + col + 1]   = acc[mi][nj][1];
            cs[(row+8)*65 + col]   = acc[mi][nj][2];
            cs[(row+8)*65 + col+1] = acc[mi][nj][3];
        }
    __syncthreads();
#pragma unroll 4
    for (int it = 0; it < 32; it++) {
        int linear = it*256 + tid;
        int col = linear >> 7, row = linear & 127;
        int m = bm + row, o = bn + col;
        int nimg = m / PIX_PER_IMG;
        int rem  = m - nimg * PIX_PER_IMG;
        out[(size_t)nimg*ODIM*PIX_PER_IMG + (size_t)o*PIX_PER_IMG + rem] =
            cs[row*65 + col] + __ldg(pb + o);
    }
}

// ---------------------------------------------------------------------------
extern "C" void kernel_launch(void* const* d_in, const int* in_sizes, int n_in,
                              void* d_out, int out_size) {
    const float* x   = (const float*)d_in[0];
    const float* pw  = (const float*)d_in[1];
    const float* pb  = (const float*)d_in[2];
    const float* sw  = (const float*)d_in[3];
    const float* sb  = (const float*)d_in[4];
    const float* lnw = (const float*)d_in[5];
    const float* lnb = (const float*)d_in[6];
    float* out = (float*)d_out;

    cudaFuncSetAttribute(hmma_gemm_kernel,
                         cudaFuncAttributeMaxDynamicSharedMemorySize, DSMEM_B);

    score_prep_kernel<<<1536, 256>>>(x, sw, sb, pw);
    attn_agg_kernel<<<NIMG*HH*4, 128>>>(x, lnw, lnb);
    dim3 grid(NWIN/BM /*49*/, ODIM/BN /*8*/);
    hmma_gemm_kernel<<<grid, 256, DSMEM_B>>>(pb, out);
}

// round 6
// speedup vs baseline: 4.8163x; 1.3304x over previous
#include <cuda_runtime.h>
#include <cuda_fp16.h>
#include <cstdint>

#define NIMG 8
#define CDIM 512
#define HDIM 32
#define WDIM 32
#define ODIM 512
#define KW   5
#define HH   28
#define WWN  28
#define NWIN (NIMG*HH*WWN)      // 6272
#define NPIX (NIMG*HDIM*WDIM)   // 8192
#define PIX_PER_IMG (HH*WWN)    // 784
#define LNEPS 1e-5f

// ---------------- scratch (no allocations allowed) ----------------
__device__ float g_score[NPIX];
__device__ __half g_xa_h[(size_t)NWIN * CDIM];   // 6.4MB
__device__ __half g_pw_h[ODIM * CDIM];

__device__ __forceinline__ uint32_t s2u(const void* p) {
    return (uint32_t)__cvta_generic_to_shared(p);
}
__device__ __forceinline__ void ldmx4(uint32_t r[4], uint32_t a) {
    asm volatile("ldmatrix.sync.aligned.m8n8.x4.shared.b16 {%0,%1,%2,%3}, [%4];"
        : "=r"(r[0]), "=r"(r[1]), "=r"(r[2]), "=r"(r[3]) : "r"(a));
}
__device__ __forceinline__ void mma16816(float d[4], const uint32_t a[4], const uint32_t b[2]) {
    asm volatile("mma.sync.aligned.m16n8k16.row.col.f32.f16.f16.f32 "
        "{%0,%1,%2,%3}, {%4,%5,%6,%7}, {%8,%9}, {%0,%1,%2,%3};"
        : "+f"(d[0]), "+f"(d[1]), "+f"(d[2]), "+f"(d[3])
        : "r"(a[0]), "r"(a[1]), "r"(a[2]), "r"(a[3]), "r"(b[0]), "r"(b[1]));
}
__device__ __forceinline__ void cpasync16(uint32_t s, const void* g) {
    asm volatile("cp.async.cg.shared.global [%0], [%1], 16;" :: "r"(s), "l"(g));
}
#define CP_COMMIT() asm volatile("cp.async.commit_group;" ::: "memory")
#define CP_WAIT1()  asm volatile("cp.async.wait_group 1;" ::: "memory")

// ---------------------------------------------------------------------------
// K1 (fused): blocks [0,256): score GEMV, 4 pixels per warp (MLP=16+/thread);
//             blocks [256,1280): proj_w fp16 cast
// ---------------------------------------------------------------------------
__global__ void score_prep_kernel(const float* __restrict__ x,
                                  const float* __restrict__ sw,
                                  const float* __restrict__ sb,
                                  const float* __restrict__ pw) {
    if (blockIdx.x >= 256) {
        int i = (blockIdx.x - 256) * 256 + threadIdx.x;   // < 262144
        g_pw_h[i] = __float2half(pw[i]);
        return;
    }
    int gw   = blockIdx.x * 8 + (threadIdx.x >> 5);  // 0..2047
    int lane = threadIdx.x & 31;
    int p0 = gw * 4;
    const float4* xb = (const float4*)(x + (size_t)p0 * CDIM);
    const float4* w4 = (const float4*)sw;
    float a0 = 0.f, a1 = 0.f, a2 = 0.f, a3 = 0.f;
#pragma unroll
    for (int i = 0; i < 4; i++) {
        float4 vw = __ldg(w4 + lane + 32*i);
        float4 v0 = __ldg(xb + lane + 32*i);
        float4 v1 = __ldg(xb + lane + 32*i + 128);
        float4 v2 = __ldg(xb + lane + 32*i + 256);
        float4 v3 = __ldg(xb + lane + 32*i + 384);
        a0 += v0.x*vw.x + v0.y*vw.y + v0.z*vw.z + v0.w*vw.w;
        a1 += v1.x*vw.x + v1.y*vw.y + v1.z*vw.z + v1.w*vw.w;
        a2 += v2.x*vw.x + v2.y*vw.y + v2.z*vw.z + v2.w*vw.w;
        a3 += v3.x*vw.x + v3.y*vw.y + v3.z*vw.z + v3.w*vw.w;
    }
#pragma unroll
    for (int o = 16; o; o >>= 1) {
        a0 += __shfl_xor_sync(0xffffffffu, a0, o);
        a1 += __shfl_xor_sync(0xffffffffu, a1, o);
        a2 += __shfl_xor_sync(0xffffffffu, a2, o);
        a3 += __shfl_xor_sync(0xffffffffu, a3, o);
    }
    if (lane == 0) {
        float b = sb[0];
        g_score[p0]   = a0 + b;
        g_score[p0+1] = a1 + b;
        g_score[p0+2] = a2 + b;
        g_score[p0+3] = a3 + b;
    }
}

// ---------------------------------------------------------------------------
// K2: 4x7 windows per block (one 8x11 pixel patch). LN+softmax per window,
//     stream 88 pixel-rows once, accumulate all 28 windows. fp16 out.
// ---------------------------------------------------------------------------
__global__ __launch_bounds__(128)
void attn_agg_kernel(const float* __restrict__ x,
                     const float* __restrict__ lnw,
                     const float* __restrict__ lnb) {
    const int b  = blockIdx.x;           // NIMG*7*4 = 224
    const int n  = b / 28;
    const int rb = b % 28;
    const int hh0 = (rb >> 2) * 4;       // 0,4,...,24
    const int ww0 = (rb & 3) * 7;        // 0,7,14,21
    const int t = threadIdx.x;

    __shared__ float s[8][11];
    __shared__ float wgt[28][25];
    if (t < 88) {
        int ki = t / 11, kj = t % 11;
        s[ki][kj] = g_score[(n*HDIM + hh0 + ki)*WDIM + ww0 + kj];
    }
    __syncthreads();
    if (t < 28) {
        int wr = t / 7, wc = t % 7;
        float sc[25];
#pragma unroll
        for (int a = 0; a < 5; a++)
#pragma unroll
            for (int c = 0; c < 5; c++) sc[a*5+c] = s[wr+a][wc+c];
        float mu = 0.f;
#pragma unroll
        for (int k = 0; k < 25; k++) mu += sc[k];
        mu *= (1.f/25.f);
        float var = 0.f;
#pragma unroll
        for (int k = 0; k < 25; k++) { float d = sc[k]-mu; var += d*d; }
        var *= (1.f/25.f);
        float inv = rsqrtf(var + LNEPS);
        float e[25], mx = -1e30f;
#pragma unroll
        for (int k = 0; k < 25; k++) {
            float z = (sc[k]-mu)*inv*lnw[k] + lnb[k];
            e[k] = z; mx = fmaxf(mx, z);
        }
        float sum = 0.f;
#pragma unroll
        for (int k = 0; k < 25; k++) { e[k] = __expf(e[k]-mx); sum += e[k]; }
        float rs = 1.f/sum;
#pragma unroll
        for (int k = 0; k < 25; k++) wgt[t][k] = e[k]*rs;
    }
    __syncthreads();

    float4 acc[4][7];
#pragma unroll
    for (int wr = 0; wr < 4; wr++)
#pragma unroll
        for (int wc = 0; wc < 7; wc++) acc[wr][wc] = make_float4(0.f,0.f,0.f,0.f);

#pragma unroll
    for (int ki = 0; ki < 8; ki++) {
        const float4* rbp = (const float4*)(x +
            ((size_t)((n*HDIM + hh0 + ki)*WDIM + ww0)) * CDIM) + t;
#pragma unroll
        for (int kj = 0; kj < 11; kj++) {
            float4 v = __ldg(rbp + kj*(CDIM/4));
#pragma unroll
            for (int wr = 0; wr < 4; wr++) {
                if (ki - wr < 0 || ki - wr > 4) continue;
#pragma unroll
                for (int wc = 0; wc < 7; wc++) {
                    if (kj - wc < 0 || kj - wc > 4) continue;
                    float wk = wgt[wr*7 + wc][(ki-wr)*5 + (kj-wc)];
                    acc[wr][wc].x += wk*v.x; acc[wr][wc].y += wk*v.y;
                    acc[wr][wc].z += wk*v.z; acc[wr][wc].w += wk*v.w;
                }
            }
        }
    }

#pragma unroll
    for (int wr = 0; wr < 4; wr++)
#pragma unroll
        for (int wc = 0; wc < 7; wc++) {
            int win = (n*HH + hh0 + wr)*WWN + ww0 + wc;
            size_t base = (size_t)win*CDIM + t*4;
            __half2 H0; H0.x = __float2half(acc[wr][wc].x); H0.y = __float2half(acc[wr][wc].y);
            __half2 H1; H1.x = __float2half(acc[wr][wc].z); H1.y = __float2half(acc[wr][wc].w);
            *(__half2*)(g_xa_h + base)     = H0;
            *(__half2*)(g_xa_h + base + 2) = H1;
        }
}

// ---------------------------------------------------------------------------
// K3: plain fp16 HMMA GEMM. CTA 128x64, KCH=64, SW128 swizzle, 3-stage
//     cp.async, 8 warps (32x32 warp tile), 3 CTAs/SM -> single wave.
// ---------------------------------------------------------------------------
#define BM 128
#define BN 64
#define KCH 64
#define NCH (CDIM/KCH)            // 8
#define ATILE_B (BM*128)          // 16384
#define BTILE_B (BN*128)          // 8192
#define STAGE_B (ATILE_B + BTILE_B)   // 24576
#define NSTG 3
#define DSMEM_B (NSTG*STAGE_B)    // 73728 >= epi 33280

__global__ __launch_bounds__(256, 3)
void hmma_gemm_kernel(const float* __restrict__ pb, float* __restrict__ out) {
    extern __shared__ char dsm[];
    const int tid = threadIdx.x, wid = tid >> 5, lane = tid & 31;
    const int bm = blockIdx.x * BM, bn = blockIdx.y * BN;
    const int m_org = (wid & 3) * 32;
    const int n_org = (wid >> 2) * 32;
    const int quad = lane >> 3, rq = lane & 7;

    float acc[2][4][4];
#pragma unroll
    for (int a = 0; a < 2; a++)
#pragma unroll
        for (int b = 0; b < 4; b++)
#pragma unroll
            for (int c = 0; c < 4; c++) acc[a][b][c] = 0.f;

    auto ISSUE = [&](int ck) {
        if (ck < NCH) {
            const int k0 = ck * KCH;
            char* buf = dsm + (ck % NSTG) * STAGE_B;
#pragma unroll
            for (int i = 0; i < 6; i++) {
                int idx = tid + i*256;             // 0..1535
                if (idx < 1024) {                  // A: 128 rows x 8 chunks
                    int r = idx >> 3, j = idx & 7;
                    uint32_t off = (uint32_t)(r*128 + j*16);
                    off ^= (off >> 3) & 0x70;
                    cpasync16(s2u(buf + off),
                              g_xa_h + (size_t)(bm + r)*CDIM + k0 + j*8);
                } else {                           // B: 64 rows x 8 chunks
                    int c = idx - 1024, r = c >> 3, j = c & 7;
                    uint32_t off = (uint32_t)(r*128 + j*16);
                    off ^= (off >> 3) & 0x70;
                    cpasync16(s2u(buf + ATILE_B + off),
                              g_pw_h + (size_t)(bn + r)*CDIM + k0 + j*8);
                }
            }
        }
        CP_COMMIT();
    };

    ISSUE(0);
    ISSUE(1);
    for (int ck = 0; ck < NCH; ck++) {
        char* buf = dsm + (ck % NSTG) * STAGE_B;
        CP_WAIT1();
        __syncthreads();
        ISSUE(ck + 2);

        const uint32_t abase = s2u(buf);
        const uint32_t bbase = s2u(buf + ATILE_B);
#pragma unroll
        for (int ks = 0; ks < 4; ks++) {
            const int jA = ks * 2;
            uint32_t ah[2][4];
#pragma unroll
            for (int mi = 0; mi < 2; mi++) {
                int row = m_org + mi*16 + rq + ((quad & 1) << 3);
                int jh = jA + (quad >> 1);
                uint32_t o = (uint32_t)(row*128 + jh*16); o ^= (o >> 3) & 0x70;
                ldmx4(ah[mi], abase + o);
            }
            uint32_t bh[2][4];
#pragma unroll
            for (int nb = 0; nb < 2; nb++) {
                int row = n_org + nb*16 + rq + ((quad >> 1) << 3);
                int jh = jA + (quad & 1);
                uint32_t o = (uint32_t)(row*128 + jh*16); o ^= (o >> 3) & 0x70;
                ldmx4(bh[nb], bbase + o);
            }
#pragma unroll
            for (int mi = 0; mi < 2; mi++)
#pragma unroll
                for (int nj = 0; nj < 4; nj++)
                    mma16816(acc[mi][nj], ah[mi], &bh[nj >> 1][(nj & 1) * 2]);
        }
        __syncthreads();
    }

    // epilogue: transpose through smem for coalesced (o-major) global stores
    float* cs = (float*)dsm;
#pragma unroll
    for (int mi = 0; mi < 2; mi++)
#pragma unroll
        for (int nj = 0; nj < 4; nj++) {
            int row = m_org + mi*16 + (lane >> 2);
            int col = n_org + nj*8 + 2*(lane & 3);
            cs[row*65 + col]       = acc[mi][nj][0];
            cs[row*65 + col + 1]   = acc[mi][nj][1];
            cs[(row+8)*65 + col]   = acc[mi][nj][2];
            cs[(row+8)*65 + col+1] = acc[mi][nj][3];
        }
    __syncthreads();
#pragma unroll 4
    for (int it = 0; it < 32; it++) {
        int linear = it*256 + tid;
        int col = linear >> 7, row = linear & 127;
        int m = bm + row, o = bn + col;
        int nimg = m / PIX_PER_IMG;
        int rem  = m - nimg * PIX_PER_IMG;
        out[(size_t)nimg*ODIM*PIX_PER_IMG + (size_t)o*PIX_PER_IMG + rem] =
            cs[row*65 + col] + __ldg(pb + o);
    }
}

// ---------------------------------------------------------------------------
extern "C" void kernel_launch(void* const* d_in, const int* in_sizes, int n_in,
                              void* d_out, int out_size) {
    const float* x   = (const float*)d_in[0];
    const float* pw  = (const float*)d_in[1];
    const float* pb  = (const float*)d_in[2];
    const float* sw  = (const float*)d_in[3];
    const float* sb  = (const float*)d_in[4];
    const float* lnw = (const float*)d_in[5];
    const float* lnb = (const float*)d_in[6];
    float* out = (float*)d_out;

    cudaFuncSetAttribute(hmma_gemm_kernel,
                         cudaFuncAttributeMaxDynamicSharedMemorySize, DSMEM_B);

    score_prep_kernel<<<1280, 256>>>(x, sw, sb, pw);
    attn_agg_kernel<<<NIMG*7*4, 128>>>(x, lnw, lnb);
    dim3 grid(NWIN/BM /*49*/, ODIM/BN /*8*/);
    hmma_gemm_kernel<<<grid, 256, DSMEM_B>>>(pb, out);
}